// round 15
// baseline (speedup 1.0000x reference)
#include <cuda_runtime.h>
#include <cuda_fp16.h>
#include <cstdint>

constexpr int SEQ   = 2048;
constexpr int CH    = 1024;
constexpr int NHEAD = 16;
constexpr int HDIM  = 64;

// ---------------------------------------------------------------------------
// Scratch
// ---------------------------------------------------------------------------
__device__ __half g_xh[SEQ * CH];                            // x -> half, [w][c]
__device__ __half g_wth[4][CH * CH], g_wtl[4][CH * CH];      // W^T split, [n][k]
__device__ __half g_erth[SEQ * HDIM];                        // er^T hi, [i][d]
__device__ float  g_q0[SEQ * CH], g_k0[SEQ * CH], g_v0[SEQ * CH];
__device__ __half g_qch[SEQ * CH], g_qcl[SEQ * CH];          // conv(q) split, [w][c]
__device__ __half g_kch[SEQ * CH], g_kcl[SEQ * CH];
__device__ float  g_vc[SEQ * CH];                            // conv(v) fp32
__device__ __half g_vth[CH * SEQ], g_vtl[CH * SEQ];          // conv(v)^T split, [c][w]
__device__ __half g_Sh[(long long)NHEAD * SEQ * SEQ];        // half scores -> probs (in-place)
__device__ __half g_ath[SEQ * CH];                           // attn half, [w][c]

// ---------------------------------------------------------------------------
// Helpers
// ---------------------------------------------------------------------------
__device__ __forceinline__ uint32_t smem_u32(const void* p) {
    uint32_t a;
    asm("{ .reg .u64 t; cvta.to.shared.u64 t, %1; cvt.u32.u64 %0, t; }" : "=r"(a) : "l"(p));
    return a;
}
__device__ __forceinline__ void split_h(float x, __half& h, __half& l) {
    h = __float2half_rn(x);
    l = __float2half_rn(x - __half2float(h));
}
__device__ __forceinline__ void mma_f16(float* c, const uint32_t* a, const uint32_t* b) {
    asm volatile(
        "mma.sync.aligned.m16n8k16.row.col.f32.f16.f16.f32 "
        "{%0,%1,%2,%3},{%4,%5,%6,%7},{%8,%9},{%0,%1,%2,%3};"
        : "+f"(c[0]), "+f"(c[1]), "+f"(c[2]), "+f"(c[3])
        : "r"(a[0]), "r"(a[1]), "r"(a[2]), "r"(a[3]), "r"(b[0]), "r"(b[1]));
}
__device__ __forceinline__ void ldsm_x4(uint32_t* r, uint32_t addr) {
    asm volatile("ldmatrix.sync.aligned.m8n8.x4.shared.b16 {%0,%1,%2,%3}, [%4];"
        : "=r"(r[0]), "=r"(r[1]), "=r"(r[2]), "=r"(r[3]) : "r"(addr));
}
__device__ __forceinline__ void cpa16(uint32_t s, const void* g) {
    asm volatile("cp.async.ca.shared.global [%0], [%1], 16;" :: "r"(s), "l"(g));
}
#define CP_COMMIT() asm volatile("cp.async.commit_group;" ::: "memory")
#define CP_WAIT1()  asm volatile("cp.async.wait_group 1;" ::: "memory")

struct KtH { const __half* ah; const __half* al; const __half* bh; const __half* bl;
             int lda; int ldb; };

// ---------------------------------------------------------------------------
// 3-stage cp.async pipelined FP16 GEMM body, k-tile = 32, ONE barrier per
// k-tile (issue into the slot freed last iteration, guarded by the top sync).
// B fragments: paired ldmatrix.x4 (two n-tiles per instruction).
// Row stride 80 B (conflict-free for cp.async stores and ldmatrix reads).
// ASPL: A hi/lo split (x3 MMAs) or single A (x2 MMAs: ah*bh + ah*bl).
// OMODE: 0 = fp32 C, 1 = split half Ch/Cl, 2 = half Ch only.
// ---------------------------------------------------------------------------
template<int BM, int BN, int WM, int WN, bool ASPL, int OMODE, typename F>
__device__ __forceinline__ void gemm_pipe(
    F&& ktf, int KT, float* C, __half* Ch, __half* Cl, int ldc, float alpha, char* sm_)
{
    constexpr int WARPS_M = BM / WM, WARPS_N = BN / WN;
    static_assert(WARPS_M * WARPS_N == 8, "");
    constexpr int MT = WM / 16, NT = WN / 8;
    static_assert((NT & 1) == 0, "paired B ldsm needs even NT");
    constexpr int ROWB = 80;                        // 32 halfs + 16B pad
    constexpr int ABYT = BM * ROWB, BBYT = BN * ROWB;
    constexpr int NAARR = ASPL ? 2 : 1;
    constexpr int STB  = NAARR * ABYT + 2 * BBYT;

    const uint32_t sb = smem_u32(sm_);
    const int tid = threadIdx.x, wid = tid >> 5, lane = tid & 31;
    const int gid = lane >> 2, tig = lane & 3;
    const int wm0 = (wid % WARPS_M) * WM, wn0 = (wid / WARPS_M) * WN;

    auto issue = [&](int s, int t) {
        KtH p = ktf(t);
        uint32_t st = sb + s * STB;
        #pragma unroll
        for (int i = 0; i < BM * 4 / 256; i++) {
            int id = tid + i * 256, row = id >> 2, c16 = id & 3;
            uint32_t sa = st + row * ROWB + c16 * 16;
            cpa16(sa, p.ah + (long long)row * p.lda + c16 * 8);
            if (ASPL) cpa16(sa + ABYT, p.al + (long long)row * p.lda + c16 * 8);
        }
        #pragma unroll
        for (int i = 0; i < (BN * 4 + 255) / 256; i++) {
            int id = tid + i * 256;
            if (id < BN * 4) {
                int row = id >> 2, c16 = id & 3;
                uint32_t sa = st + NAARR * ABYT + row * ROWB + c16 * 16;
                cpa16(sa,        p.bh + (long long)row * p.ldb + c16 * 8);
                cpa16(sa + BBYT, p.bl + (long long)row * p.ldb + c16 * 8);
            }
        }
    };

    float acc[MT][NT][4] = {};

    // prologue: stages 0 and 1
    issue(0, 0); CP_COMMIT();
    if (KT > 1) issue(1, 1);
    CP_COMMIT();

    for (int t = 0; t < KT; t++) {
        CP_WAIT1();                 // stage t complete (newest in flight = t+1)
        __syncthreads();            // slot (t+2)%3 fully consumed last iter
        if (t + 2 < KT) issue((t + 2) % 3, t + 2);
        CP_COMMIT();

        uint32_t base = sb + (t % 3) * STB;
        #pragma unroll
        for (int ck = 0; ck < 2; ck++) {            // two 16-k chunks per stage
            uint32_t co = (uint32_t)ck * 32;
            uint32_t ah[MT][4], al[MT][4], bh[NT][2], bl[NT][2];
            #pragma unroll
            for (int mt = 0; mt < MT; mt++) {
                uint32_t a0 = base + (wm0 + mt * 16 + (lane & 15)) * ROWB + co
                            + (lane >> 4) * 16;
                ldsm_x4(ah[mt], a0);
                if (ASPL) ldsm_x4(al[mt], a0 + ABYT);
            }
            #pragma unroll
            for (int np = 0; np < NT / 2; np++) {
                // paired x4: mats {0,1} = 16 rows at col-half 0, {2,3} at col-half 1
                int sel = (lane >> 3) & 3;
                uint32_t row = wn0 + np * 16 + (sel & 1) * 8 + (lane & 7);
                uint32_t b0 = base + NAARR * ABYT + row * ROWB + co + (sel >> 1) * 16;
                uint32_t r[4];
                ldsm_x4(r, b0);
                bh[2 * np][0] = r[0]; bh[2 * np][1] = r[2];
                bh[2 * np + 1][0] = r[1]; bh[2 * np + 1][1] = r[3];
                ldsm_x4(r, b0 + BBYT);
                bl[2 * np][0] = r[0]; bl[2 * np][1] = r[2];
                bl[2 * np + 1][0] = r[1]; bl[2 * np + 1][1] = r[3];
            }
            #pragma unroll
            for (int mt = 0; mt < MT; mt++)
                #pragma unroll
                for (int nt = 0; nt < NT; nt++) {
                    mma_f16(acc[mt][nt], ah[mt], bh[nt]);
                    mma_f16(acc[mt][nt], ah[mt], bl[nt]);
                    if (ASPL) mma_f16(acc[mt][nt], al[mt], bh[nt]);
                }
        }
    }

    #pragma unroll
    for (int mt = 0; mt < MT; mt++)
        #pragma unroll
        for (int nt = 0; nt < NT; nt++) {
            int r = wm0 + mt * 16 + gid;
            int c = wn0 + nt * 8 + 2 * tig;
            #pragma unroll
            for (int half_ = 0; half_ < 2; half_++) {
                int rr = r + half_ * 8;
                float v0 = alpha * acc[mt][nt][half_ * 2 + 0];
                float v1 = alpha * acc[mt][nt][half_ * 2 + 1];
                if (OMODE == 1) {
                    __half h0, l0, h1, l1;
                    split_h(v0, h0, l0); split_h(v1, h1, l1);
                    *(__half2*)(Ch + (long long)rr * ldc + c) = __halves2half2(h0, h1);
                    *(__half2*)(Cl + (long long)rr * ldc + c) = __halves2half2(l0, l1);
                } else if (OMODE == 2) {
                    *(__half2*)(Ch + (long long)rr * ldc + c) = __floats2half2_rn(v0, v1);
                } else {
                    *(float2*)(C + (long long)rr * ldc + c) = make_float2(v0, v1);
                }
            }
        }
}

// ---------------------------------------------------------------------------
// GEMM kernels
// ---------------------------------------------------------------------------
// q/k/v projections: BN=64 tiles for wave balance (768 CTAs), x2 MMAs
__global__ __launch_bounds__(256, 2) void qkv_pipe()
{
    extern __shared__ char smem[];
    const int z = blockIdx.z;
    const int m0 = blockIdx.y * 128, n0 = blockIdx.x * 64;
    float* O = ((z == 0) ? g_q0 : (z == 1) ? g_k0 : g_v0) + (long long)m0 * CH + n0;
    const __half* Ah = g_xh + (long long)m0 * CH;
    const __half* Bh = g_wth[z] + (long long)n0 * CH;
    const __half* Bl = g_wtl[z] + (long long)n0 * CH;
    auto ktf = [&](int t) -> KtH {
        return { Ah + t * 32, Ah + t * 32, Bh + t * 32, Bl + t * 32, CH, CH };
    };
    gemm_pipe<128, 64, 32, 32, false, 0>(ktf, CH / 32, O, nullptr, nullptr, CH, 1.f, smem);
}

// output projection: BN=64 tiles (256 CTAs -> fills the chip), x2 MMAs
__global__ __launch_bounds__(256, 2) void wo_pipe(float* __restrict__ out)
{
    extern __shared__ char smem[];
    const int m0 = blockIdx.y * 128, n0 = blockIdx.x * 64;
    const __half* Ah = g_ath + (long long)m0 * CH;
    const __half* Bh = g_wth[3] + (long long)n0 * CH;
    const __half* Bl = g_wtl[3] + (long long)n0 * CH;
    float* O = out + (long long)m0 * CH + n0;
    auto ktf = [&](int t) -> KtH {
        return { Ah + t * 32, Ah + t * 32, Bh + t * 32, Bl + t * 32, CH, CH };
    };
    gemm_pipe<128, 64, 32, 32, false, 0>(ktf, CH / 32, O, nullptr, nullptr, CH, 1.f, smem);
}

// Score: S[h,i,j] = ( q_i.k_j + erT_i.q_j ) / 32 — virtual K = 128 (4 x 32), x2
__global__ __launch_bounds__(256, 2) void score_pipe()
{
    extern __shared__ char smem[];
    const int h = blockIdx.z, cb = h * HDIM;
    const int i0 = blockIdx.y * 128, j0 = blockIdx.x * 128;
    __half* O = g_Sh + ((long long)h * SEQ + i0) * SEQ + j0;
    auto ktf = [&](int t) -> KtH {
        if (t < 2) {
            const __half* a = g_qch + (long long)i0 * CH + cb + t * 32;
            return { a, a,
                     g_kch + (long long)j0 * CH + cb + t * 32,
                     g_kcl + (long long)j0 * CH + cb + t * 32, CH, CH };
        }
        int d0 = (t - 2) * 32;
        const __half* a = g_erth + (long long)i0 * HDIM + d0;
        return { a, a,
                 g_qch + (long long)j0 * CH + cb + d0,
                 g_qcl + (long long)j0 * CH + cb + d0, HDIM, CH };
    };
    gemm_pipe<128, 128, 64, 32, false, 2>(ktf, 4, nullptr, O, nullptr, SEQ, 0.03125f, smem);
}

// A @ V per head: A = probs (half single), B = V^T split. Half output.
__global__ __launch_bounds__(256, 2) void av_pipe()
{
    extern __shared__ char smem[];
    const int h = blockIdx.z;
    const int m0 = blockIdx.y * 128;
    const __half* Ah = g_Sh + ((long long)h * SEQ + m0) * SEQ;
    const __half* Bh = g_vth + (long long)(h * HDIM) * SEQ;
    const __half* Bl = g_vtl + (long long)(h * HDIM) * SEQ;
    __half* Oh = g_ath + (long long)m0 * CH + h * HDIM;
    auto ktf = [&](int t) -> KtH {
        return { Ah + t * 32, Ah + t * 32, Bh + t * 32, Bl + t * 32, SEQ, SEQ };
    };
    gemm_pipe<128, 64, 32, 32, false, 2>(ktf, SEQ / 32, nullptr, Oh, nullptr, CH, 1.f, smem);
}

// ---------------------------------------------------------------------------
// Prep kernels
// ---------------------------------------------------------------------------
__global__ __launch_bounds__(256) void split_x(const float* __restrict__ x)
{
    int i = blockIdx.x * 256 + threadIdx.x;
    if (i >= SEQ * CH) return;
    g_xh[i] = __float2half_rn(x[i]);
}

__device__ __forceinline__ void tsplit_body(
    const float* __restrict__ in, __half* __restrict__ oh, __half* __restrict__ ol,
    int R, int C)
{
    __shared__ float t[32][33];
    int c0 = blockIdx.x * 32, r0 = blockIdx.y * 32;
    int tx = threadIdx.x, ty = threadIdx.y;   // 32 x 8
    #pragma unroll
    for (int j = 0; j < 4; j++)
        t[ty + 8 * j][tx] = in[(long long)(r0 + ty + 8 * j) * C + c0 + tx];
    __syncthreads();
    #pragma unroll
    for (int j = 0; j < 4; j++) {
        float v = t[tx][ty + 8 * j];
        __half h, l; split_h(v, h, l);
        long long o = (long long)(c0 + ty + 8 * j) * R + r0 + tx;
        oh[o] = h;
        if (ol) ol[o] = l;
    }
}

__global__ void transpose_split(const float* __restrict__ in,
                                __half* __restrict__ oh, __half* __restrict__ ol,
                                int R, int C)
{
    tsplit_body(in, oh, ol, R, C);
}

__global__ void transpose_split_w4(const float* __restrict__ w0,
                                   const float* __restrict__ w1,
                                   const float* __restrict__ w2,
                                   const float* __restrict__ w3)
{
    const int z = blockIdx.z;
    const float* in = (z == 0) ? w0 : (z == 1) ? w1 : (z == 2) ? w2 : w3;
    tsplit_body(in, g_wth[z], g_wtl[z], CH, CH);
}

__global__ __launch_bounds__(256) void dwconv3(const float* __restrict__ cw)
{
    const int z = blockIdx.y;
    const float* X = (z == 0) ? g_q0 : (z == 1) ? g_k0 : g_v0;
    int idx = blockIdx.x * 256 + threadIdx.x;
    if (idx >= SEQ * CH) return;
    int c = idx & (CH - 1);
    int w = idx >> 10;
    float w0 = cw[c * 3 + 0], w1 = cw[c * 3 + 1], w2 = cw[c * 3 + 2];
    float acc = X[idx] * w1;
    if (w > 0)       acc += X[idx - CH] * w0;
    if (w < SEQ - 1) acc += X[idx + CH] * w2;
    if (z == 2) { g_vc[idx] = acc; return; }
    __half h, l; split_h(acc, h, l);
    if (z == 0) { g_qch[idx] = h; g_qcl[idx] = l; }
    else        { g_kch[idx] = h; g_kcl[idx] = l; }
}

// ---------------------------------------------------------------------------
// Softmax over half rows of g_Sh, in place.
// ---------------------------------------------------------------------------
__global__ __launch_bounds__(256) void softmax_rows()
{
    long long ro = ((long long)blockIdx.y * SEQ + blockIdx.x) * SEQ;
    uint4* row4 = (uint4*)(g_Sh + ro);
    const int tid = threadIdx.x;
    __shared__ float red[8];

    uint4 raw = row4[tid];
    __half2 hp[4] = { *(__half2*)&raw.x, *(__half2*)&raw.y,
                      *(__half2*)&raw.z, *(__half2*)&raw.w };
    float v[8];
    #pragma unroll
    for (int i = 0; i < 4; i++) {
        float2 f = __half22float2(hp[i]);
        v[2 * i] = f.x; v[2 * i + 1] = f.y;
    }

    float m = v[0];
    #pragma unroll
    for (int i = 1; i < 8; i++) m = fmaxf(m, v[i]);
    #pragma unroll
    for (int s = 16; s > 0; s >>= 1) m = fmaxf(m, __shfl_xor_sync(~0u, m, s));
    if ((tid & 31) == 0) red[tid >> 5] = m;
    __syncthreads();
    m = red[0];
    #pragma unroll
    for (int i = 1; i < 8; i++) m = fmaxf(m, red[i]);
    __syncthreads();

    float sum = 0.f;
    #pragma unroll
    for (int i = 0; i < 8; i++) { v[i] = __expf(v[i] - m); sum += v[i]; }
    #pragma unroll
    for (int s = 16; s > 0; s >>= 1) sum += __shfl_xor_sync(~0u, sum, s);
    if ((tid & 31) == 0) red[tid >> 5] = sum;
    __syncthreads();
    sum = 0.f;
    #pragma unroll
    for (int i = 0; i < 8; i++) sum += red[i];
    float inv = 1.0f / sum;

    uint4 outp;
    __half2* op = (__half2*)&outp;
    #pragma unroll
    for (int i = 0; i < 4; i++)
        op[i] = __floats2half2_rn(v[2 * i] * inv, v[2 * i + 1] * inv);
    row4[tid] = outp;
}

// ---------------------------------------------------------------------------
// Launch
// ---------------------------------------------------------------------------
extern "C" void kernel_launch(void* const* d_in, const int* in_sizes, int n_in,
                              void* d_out, int out_size)
{
    const float* x  = (const float*)d_in[0];
    const float* wq = (const float*)d_in[1];
    const float* wk = (const float*)d_in[2];
    const float* wv = (const float*)d_in[3];
    const float* wo = (const float*)d_in[4];
    const float* cw = (const float*)d_in[5];
    const float* er = (const float*)d_in[6];
    float* out = (float*)d_out;

    __half *erth, *vth, *vtl;
    float* vc;
    cudaGetSymbolAddress((void**)&erth, g_erth);
    cudaGetSymbolAddress((void**)&vth,  g_vth);
    cudaGetSymbolAddress((void**)&vtl,  g_vtl);
    cudaGetSymbolAddress((void**)&vc,   g_vc);

    const int SM64  = (1 * 128 + 2 * 64) * 80 * 3;   // 61,440  (qkv/wo/av)
    const int SM128 = (1 * 128 + 2 * 128) * 80 * 3;  // 92,160  (score)
    cudaFuncSetAttribute(qkv_pipe,   cudaFuncAttributeMaxDynamicSharedMemorySize, SM64);
    cudaFuncSetAttribute(wo_pipe,    cudaFuncAttributeMaxDynamicSharedMemorySize, SM64);
    cudaFuncSetAttribute(score_pipe, cudaFuncAttributeMaxDynamicSharedMemorySize, SM128);
    cudaFuncSetAttribute(av_pipe,    cudaFuncAttributeMaxDynamicSharedMemorySize, SM64);

    dim3 blk(256);
    dim3 tblk(32, 8);

    // prep: x -> half; fused transpose-split of all four weights; er^T hi only
    split_x<<<SEQ * CH / 256, blk>>>(x);
    transpose_split_w4<<<dim3(32, 32, 4), tblk>>>(wq, wk, wv, wo);
    transpose_split<<<dim3(64, 2), tblk>>>(er, erth, nullptr, HDIM, SEQ);

    // q/k/v projections (x2, BN=64)
    qkv_pipe<<<dim3(CH / 64, SEQ / 128, 3), blk, SM64>>>();

    // depthwise conv (reference applies q_conv to q, k AND v)
    dwconv3<<<dim3(SEQ * CH / 256, 3), blk>>>(cw);
    transpose_split<<<dim3(32, 64), tblk>>>(vc, vth, vtl, SEQ, CH);

    // scores (x2, half out) + softmax (in place) + A@V (x2, half out)
    score_pipe<<<dim3(SEQ / 128, SEQ / 128, NHEAD), blk, SM128>>>();
    softmax_rows<<<dim3(SEQ, NHEAD), blk>>>();
    av_pipe<<<dim3(1, SEQ / 128, NHEAD), blk, SM64>>>();

    // output projection (x2, BN=64)
    wo_pipe<<<dim3(CH / 64, SEQ / 128, 1), blk, SM64>>>(out);
}

// round 16
// speedup vs baseline: 1.1619x; 1.1619x over previous
#include <cuda_runtime.h>
#include <cuda_fp16.h>
#include <cstdint>

constexpr int SEQ   = 2048;
constexpr int CH    = 1024;
constexpr int NHEAD = 16;
constexpr int HDIM  = 64;

// ---------------------------------------------------------------------------
// Scratch
// ---------------------------------------------------------------------------
__device__ __half g_xh[SEQ * CH];                            // x -> half, [w][c]
__device__ __half g_wth[4][CH * CH], g_wtl[4][CH * CH];      // W^T split, [n][k] (lo used by wo only)
__device__ __half g_erth[SEQ * HDIM];                        // er^T hi, [i][d]
__device__ float  g_q0[SEQ * CH], g_k0[SEQ * CH], g_v0[SEQ * CH];
__device__ __half g_qch[SEQ * CH];                           // conv(q) hi, [w][c]
__device__ __half g_kch[SEQ * CH], g_kcl[SEQ * CH];          // conv(k) split
__device__ __half g_qcl[SEQ * CH];                           // conv(q) lo (score B operand)
__device__ float  g_vc[SEQ * CH];                            // conv(v) fp32
__device__ __half g_vth[CH * SEQ];                           // conv(v)^T hi, [c][w]
__device__ __half g_Sh[(long long)NHEAD * SEQ * SEQ];        // half scores -> probs (in-place)
__device__ __half g_ath[SEQ * CH];                           // attn half, [w][c]

// ---------------------------------------------------------------------------
// Helpers
// ---------------------------------------------------------------------------
__device__ __forceinline__ uint32_t smem_u32(const void* p) {
    uint32_t a;
    asm("{ .reg .u64 t; cvta.to.shared.u64 t, %1; cvt.u32.u64 %0, t; }" : "=r"(a) : "l"(p));
    return a;
}
__device__ __forceinline__ void split_h(float x, __half& h, __half& l) {
    h = __float2half_rn(x);
    l = __float2half_rn(x - __half2float(h));
}
__device__ __forceinline__ void mma_f16(float* c, const uint32_t* a, const uint32_t* b) {
    asm volatile(
        "mma.sync.aligned.m16n8k16.row.col.f32.f16.f16.f32 "
        "{%0,%1,%2,%3},{%4,%5,%6,%7},{%8,%9},{%0,%1,%2,%3};"
        : "+f"(c[0]), "+f"(c[1]), "+f"(c[2]), "+f"(c[3])
        : "r"(a[0]), "r"(a[1]), "r"(a[2]), "r"(a[3]), "r"(b[0]), "r"(b[1]));
}
__device__ __forceinline__ void ldsm_x4(uint32_t* r, uint32_t addr) {
    asm volatile("ldmatrix.sync.aligned.m8n8.x4.shared.b16 {%0,%1,%2,%3}, [%4];"
        : "=r"(r[0]), "=r"(r[1]), "=r"(r[2]), "=r"(r[3]) : "r"(addr));
}
__device__ __forceinline__ void cpa16(uint32_t s, const void* g) {
    asm volatile("cp.async.ca.shared.global [%0], [%1], 16;" :: "r"(s), "l"(g));
}
#define CP_COMMIT() asm volatile("cp.async.commit_group;" ::: "memory")
#define CP_WAIT1()  asm volatile("cp.async.wait_group 1;" ::: "memory")

struct KtH { const __half* ah; const __half* al; const __half* bh; const __half* bl;
             int lda; int ldb; };

// ---------------------------------------------------------------------------
// 3-stage cp.async pipelined FP16 GEMM body, k-tile = 32, one barrier/k-tile.
// ASPL: A hi/lo split.  BSPL: B hi/lo split.  (x1/x2/x3 MMA variants)
// OMODE: 0 = fp32 C, 1 = split half Ch/Cl, 2 = half Ch only.
// Row stride 80 B (conflict-free for cp.async stores and ldmatrix reads).
// ---------------------------------------------------------------------------
template<int BM, int BN, int WM, int WN, bool ASPL, bool BSPL, int OMODE, typename F>
__device__ __forceinline__ void gemm_pipe(
    F&& ktf, int KT, float* C, __half* Ch, __half* Cl, int ldc, float alpha, char* sm_)
{
    constexpr int WARPS_M = BM / WM, WARPS_N = BN / WN;
    static_assert(WARPS_M * WARPS_N == 8, "");
    constexpr int MT = WM / 16, NT = WN / 8;
    static_assert((NT & 1) == 0, "paired B ldsm needs even NT");
    constexpr int ROWB = 80;                        // 32 halfs + 16B pad
    constexpr int ABYT = BM * ROWB, BBYT = BN * ROWB;
    constexpr int NAARR = ASPL ? 2 : 1;
    constexpr int NBARR = BSPL ? 2 : 1;
    constexpr int STB  = NAARR * ABYT + NBARR * BBYT;

    const uint32_t sb = smem_u32(sm_);
    const int tid = threadIdx.x, wid = tid >> 5, lane = tid & 31;
    const int gid = lane >> 2, tig = lane & 3;
    const int wm0 = (wid % WARPS_M) * WM, wn0 = (wid / WARPS_M) * WN;

    auto issue = [&](int s, int t) {
        KtH p = ktf(t);
        uint32_t st = sb + s * STB;
        #pragma unroll
        for (int i = 0; i < BM * 4 / 256; i++) {
            int id = tid + i * 256, row = id >> 2, c16 = id & 3;
            uint32_t sa = st + row * ROWB + c16 * 16;
            cpa16(sa, p.ah + (long long)row * p.lda + c16 * 8);
            if (ASPL) cpa16(sa + ABYT, p.al + (long long)row * p.lda + c16 * 8);
        }
        #pragma unroll
        for (int i = 0; i < (BN * 4 + 255) / 256; i++) {
            int id = tid + i * 256;
            if (id < BN * 4) {
                int row = id >> 2, c16 = id & 3;
                uint32_t sa = st + NAARR * ABYT + row * ROWB + c16 * 16;
                cpa16(sa, p.bh + (long long)row * p.ldb + c16 * 8);
                if (BSPL) cpa16(sa + BBYT, p.bl + (long long)row * p.ldb + c16 * 8);
            }
        }
    };

    float acc[MT][NT][4] = {};

    issue(0, 0); CP_COMMIT();
    if (KT > 1) issue(1, 1);
    CP_COMMIT();

    for (int t = 0; t < KT; t++) {
        CP_WAIT1();
        __syncthreads();
        if (t + 2 < KT) issue((t + 2) % 3, t + 2);
        CP_COMMIT();

        uint32_t base = sb + (t % 3) * STB;
        #pragma unroll
        for (int ck = 0; ck < 2; ck++) {
            uint32_t co = (uint32_t)ck * 32;
            uint32_t ah[MT][4], al[MT][4], bh[NT][2], bl[NT][2];
            #pragma unroll
            for (int mt = 0; mt < MT; mt++) {
                uint32_t a0 = base + (wm0 + mt * 16 + (lane & 15)) * ROWB + co
                            + (lane >> 4) * 16;
                ldsm_x4(ah[mt], a0);
                if (ASPL) ldsm_x4(al[mt], a0 + ABYT);
            }
            #pragma unroll
            for (int np = 0; np < NT / 2; np++) {
                int sel = (lane >> 3) & 3;
                uint32_t row = wn0 + np * 16 + (sel & 1) * 8 + (lane & 7);
                uint32_t b0 = base + NAARR * ABYT + row * ROWB + co + (sel >> 1) * 16;
                uint32_t r[4];
                ldsm_x4(r, b0);
                bh[2 * np][0] = r[0]; bh[2 * np][1] = r[2];
                bh[2 * np + 1][0] = r[1]; bh[2 * np + 1][1] = r[3];
                if (BSPL) {
                    ldsm_x4(r, b0 + BBYT);
                    bl[2 * np][0] = r[0]; bl[2 * np][1] = r[2];
                    bl[2 * np + 1][0] = r[1]; bl[2 * np + 1][1] = r[3];
                }
            }
            #pragma unroll
            for (int mt = 0; mt < MT; mt++)
                #pragma unroll
                for (int nt = 0; nt < NT; nt++) {
                    mma_f16(acc[mt][nt], ah[mt], bh[nt]);
                    if (BSPL) mma_f16(acc[mt][nt], ah[mt], bl[nt]);
                    if (ASPL) mma_f16(acc[mt][nt], al[mt], bh[nt]);
                }
        }
    }

    #pragma unroll
    for (int mt = 0; mt < MT; mt++)
        #pragma unroll
        for (int nt = 0; nt < NT; nt++) {
            int r = wm0 + mt * 16 + gid;
            int c = wn0 + nt * 8 + 2 * tig;
            #pragma unroll
            for (int half_ = 0; half_ < 2; half_++) {
                int rr = r + half_ * 8;
                float v0 = alpha * acc[mt][nt][half_ * 2 + 0];
                float v1 = alpha * acc[mt][nt][half_ * 2 + 1];
                if (OMODE == 1) {
                    __half h0, l0, h1, l1;
                    split_h(v0, h0, l0); split_h(v1, h1, l1);
                    *(__half2*)(Ch + (long long)rr * ldc + c) = __halves2half2(h0, h1);
                    *(__half2*)(Cl + (long long)rr * ldc + c) = __halves2half2(l0, l1);
                } else if (OMODE == 2) {
                    *(__half2*)(Ch + (long long)rr * ldc + c) = __floats2half2_rn(v0, v1);
                } else {
                    *(float2*)(C + (long long)rr * ldc + c) = make_float2(v0, v1);
                }
            }
        }
}

// ---------------------------------------------------------------------------
// GEMM kernels
// ---------------------------------------------------------------------------
// q/k/v projections: pure fp16 (x1), BN=64
__global__ __launch_bounds__(256, 2) void qkv_pipe()
{
    extern __shared__ char smem[];
    const int z = blockIdx.z;
    const int m0 = blockIdx.y * 128, n0 = blockIdx.x * 64;
    float* O = ((z == 0) ? g_q0 : (z == 1) ? g_k0 : g_v0) + (long long)m0 * CH + n0;
    const __half* Ah = g_xh + (long long)m0 * CH;
    const __half* Bh = g_wth[z] + (long long)n0 * CH;
    auto ktf = [&](int t) -> KtH {
        return { Ah + t * 32, Ah + t * 32, Bh + t * 32, Bh + t * 32, CH, CH };
    };
    gemm_pipe<128, 64, 32, 32, false, false, 0>(ktf, CH / 32, O, nullptr, nullptr, CH, 1.f, smem);
}

// output projection: A single, B split (x2), BN=64
__global__ __launch_bounds__(256, 2) void wo_pipe(float* __restrict__ out)
{
    extern __shared__ char smem[];
    const int m0 = blockIdx.y * 128, n0 = blockIdx.x * 64;
    const __half* Ah = g_ath + (long long)m0 * CH;
    const __half* Bh = g_wth[3] + (long long)n0 * CH;
    const __half* Bl = g_wtl[3] + (long long)n0 * CH;
    float* O = out + (long long)m0 * CH + n0;
    auto ktf = [&](int t) -> KtH {
        return { Ah + t * 32, Ah + t * 32, Bh + t * 32, Bl + t * 32, CH, CH };
    };
    gemm_pipe<128, 64, 32, 32, false, true, 0>(ktf, CH / 32, O, nullptr, nullptr, CH, 1.f, smem);
}

// Score: A single (q-hi / erT-hi), B split (k / qj hi+lo), x2, half out
__global__ __launch_bounds__(256, 2) void score_pipe()
{
    extern __shared__ char smem[];
    const int h = blockIdx.z, cb = h * HDIM;
    const int i0 = blockIdx.y * 128, j0 = blockIdx.x * 128;
    __half* O = g_Sh + ((long long)h * SEQ + i0) * SEQ + j0;
    auto ktf = [&](int t) -> KtH {
        if (t < 2) {
            const __half* a = g_qch + (long long)i0 * CH + cb + t * 32;
            return { a, a,
                     g_kch + (long long)j0 * CH + cb + t * 32,
                     g_kcl + (long long)j0 * CH + cb + t * 32, CH, CH };
        }
        int d0 = (t - 2) * 32;
        const __half* a = g_erth + (long long)i0 * HDIM + d0;
        return { a, a,
                 g_qch + (long long)j0 * CH + cb + d0,
                 g_qcl + (long long)j0 * CH + cb + d0, HDIM, CH };
    };
    gemm_pipe<128, 128, 64, 32, false, true, 2>(ktf, 4, nullptr, O, nullptr, SEQ, 0.03125f, smem);
}

// A @ V per head: pure fp16 (x1). Half output.
__global__ __launch_bounds__(256, 2) void av_pipe()
{
    extern __shared__ char smem[];
    const int h = blockIdx.z;
    const int m0 = blockIdx.y * 128;
    const __half* Ah = g_Sh + ((long long)h * SEQ + m0) * SEQ;
    const __half* Bh = g_vth + (long long)(h * HDIM) * SEQ;
    __half* Oh = g_ath + (long long)m0 * CH + h * HDIM;
    auto ktf = [&](int t) -> KtH {
        return { Ah + t * 32, Ah + t * 32, Bh + t * 32, Bh + t * 32, SEQ, SEQ };
    };
    gemm_pipe<128, 64, 32, 32, false, false, 2>(ktf, SEQ / 32, nullptr, Oh, nullptr, CH, 1.f, smem);
}

// ---------------------------------------------------------------------------
// Prep kernels
// ---------------------------------------------------------------------------
__global__ __launch_bounds__(256) void split_x(const float* __restrict__ x)
{
    int i = blockIdx.x * 256 + threadIdx.x;
    if (i >= SEQ * CH) return;
    g_xh[i] = __float2half_rn(x[i]);
}

__device__ __forceinline__ void tsplit_body(
    const float* __restrict__ in, __half* __restrict__ oh, __half* __restrict__ ol,
    int R, int C)
{
    __shared__ float t[32][33];
    int c0 = blockIdx.x * 32, r0 = blockIdx.y * 32;
    int tx = threadIdx.x, ty = threadIdx.y;   // 32 x 8
    #pragma unroll
    for (int j = 0; j < 4; j++)
        t[ty + 8 * j][tx] = in[(long long)(r0 + ty + 8 * j) * C + c0 + tx];
    __syncthreads();
    #pragma unroll
    for (int j = 0; j < 4; j++) {
        float v = t[tx][ty + 8 * j];
        __half h, l; split_h(v, h, l);
        long long o = (long long)(c0 + ty + 8 * j) * R + r0 + tx;
        oh[o] = h;
        if (ol) ol[o] = l;
    }
}

__global__ void transpose_split(const float* __restrict__ in,
                                __half* __restrict__ oh, __half* __restrict__ ol,
                                int R, int C)
{
    tsplit_body(in, oh, ol, R, C);
}

__global__ void transpose_split_w4(const float* __restrict__ w0,
                                   const float* __restrict__ w1,
                                   const float* __restrict__ w2,
                                   const float* __restrict__ w3)
{
    const int z = blockIdx.z;
    const float* in = (z == 0) ? w0 : (z == 1) ? w1 : (z == 2) ? w2 : w3;
    // lo array only needed for wo (z == 3); skip the writes otherwise
    tsplit_body(in, g_wth[z], (z == 3) ? g_wtl[3] : nullptr, CH, CH);
}

__global__ __launch_bounds__(256) void dwconv3(const float* __restrict__ cw)
{
    const int z = blockIdx.y;
    const float* X = (z == 0) ? g_q0 : (z == 1) ? g_k0 : g_v0;
    int idx = blockIdx.x * 256 + threadIdx.x;
    if (idx >= SEQ * CH) return;
    int c = idx & (CH - 1);
    int w = idx >> 10;
    float w0 = cw[c * 3 + 0], w1 = cw[c * 3 + 1], w2 = cw[c * 3 + 2];
    float acc = X[idx] * w1;
    if (w > 0)       acc += X[idx - CH] * w0;
    if (w < SEQ - 1) acc += X[idx + CH] * w2;
    if (z == 2) { g_vc[idx] = acc; return; }
    __half h, l; split_h(acc, h, l);
    if (z == 0) { g_qch[idx] = h; g_qcl[idx] = l; }
    else        { g_kch[idx] = h; g_kcl[idx] = l; }
}

// ---------------------------------------------------------------------------
// Softmax over half rows of g_Sh, in place.
// ---------------------------------------------------------------------------
__global__ __launch_bounds__(256) void softmax_rows()
{
    long long ro = ((long long)blockIdx.y * SEQ + blockIdx.x) * SEQ;
    uint4* row4 = (uint4*)(g_Sh + ro);
    const int tid = threadIdx.x;
    __shared__ float red[8];

    uint4 raw = row4[tid];
    __half2 hp[4] = { *(__half2*)&raw.x, *(__half2*)&raw.y,
                      *(__half2*)&raw.z, *(__half2*)&raw.w };
    float v[8];
    #pragma unroll
    for (int i = 0; i < 4; i++) {
        float2 f = __half22float2(hp[i]);
        v[2 * i] = f.x; v[2 * i + 1] = f.y;
    }

    float m = v[0];
    #pragma unroll
    for (int i = 1; i < 8; i++) m = fmaxf(m, v[i]);
    #pragma unroll
    for (int s = 16; s > 0; s >>= 1) m = fmaxf(m, __shfl_xor_sync(~0u, m, s));
    if ((tid & 31) == 0) red[tid >> 5] = m;
    __syncthreads();
    m = red[0];
    #pragma unroll
    for (int i = 1; i < 8; i++) m = fmaxf(m, red[i]);
    __syncthreads();

    float sum = 0.f;
    #pragma unroll
    for (int i = 0; i < 8; i++) { v[i] = __expf(v[i] - m); sum += v[i]; }
    #pragma unroll
    for (int s = 16; s > 0; s >>= 1) sum += __shfl_xor_sync(~0u, sum, s);
    if ((tid & 31) == 0) red[tid >> 5] = sum;
    __syncthreads();
    sum = 0.f;
    #pragma unroll
    for (int i = 0; i < 8; i++) sum += red[i];
    float inv = 1.0f / sum;

    uint4 outp;
    __half2* op = (__half2*)&outp;
    #pragma unroll
    for (int i = 0; i < 4; i++)
        op[i] = __floats2half2_rn(v[2 * i] * inv, v[2 * i + 1] * inv);
    row4[tid] = outp;
}

// ---------------------------------------------------------------------------
// Launch
// ---------------------------------------------------------------------------
extern "C" void kernel_launch(void* const* d_in, const int* in_sizes, int n_in,
                              void* d_out, int out_size)
{
    const float* x  = (const float*)d_in[0];
    const float* wq = (const float*)d_in[1];
    const float* wk = (const float*)d_in[2];
    const float* wv = (const float*)d_in[3];
    const float* wo = (const float*)d_in[4];
    const float* cw = (const float*)d_in[5];
    const float* er = (const float*)d_in[6];
    float* out = (float*)d_out;

    __half *erth, *vth;
    float* vc;
    cudaGetSymbolAddress((void**)&erth, g_erth);
    cudaGetSymbolAddress((void**)&vth,  g_vth);
    cudaGetSymbolAddress((void**)&vc,   g_vc);

    const int SMQKV = (128 + 64) * 80 * 3;           // 46,080  (x1)
    const int SMWO  = (128 + 2 * 64) * 80 * 3;       // 61,440  (B split)
    const int SM128 = (128 + 2 * 128) * 80 * 3;      // 92,160  (score)
    const int SMAV  = (128 + 64) * 80 * 3;           // 46,080  (x1)
    cudaFuncSetAttribute(qkv_pipe,   cudaFuncAttributeMaxDynamicSharedMemorySize, SMQKV);
    cudaFuncSetAttribute(wo_pipe,    cudaFuncAttributeMaxDynamicSharedMemorySize, SMWO);
    cudaFuncSetAttribute(score_pipe, cudaFuncAttributeMaxDynamicSharedMemorySize, SM128);
    cudaFuncSetAttribute(av_pipe,    cudaFuncAttributeMaxDynamicSharedMemorySize, SMAV);

    dim3 blk(256);
    dim3 tblk(32, 8);

    // prep: x -> half; fused transpose-split of all four weights; er^T hi only
    split_x<<<SEQ * CH / 256, blk>>>(x);
    transpose_split_w4<<<dim3(32, 32, 4), tblk>>>(wq, wk, wv, wo);
    transpose_split<<<dim3(64, 2), tblk>>>(er, erth, nullptr, HDIM, SEQ);

    // q/k/v projections (x1, BN=64)
    qkv_pipe<<<dim3(CH / 64, SEQ / 128, 3), blk, SMQKV>>>();

    // depthwise conv (reference applies q_conv to q, k AND v)
    dwconv3<<<dim3(SEQ * CH / 256, 3), blk>>>(cw);
    transpose_split<<<dim3(32, 64), tblk>>>(vc, vth, nullptr, SEQ, CH);

    // scores (x2, half out) + softmax (in place) + A@V (x1, half out)
    score_pipe<<<dim3(SEQ / 128, SEQ / 128, NHEAD), blk, SM128>>>();
    softmax_rows<<<dim3(SEQ, NHEAD), blk>>>();
    av_pipe<<<dim3(1, SEQ / 128, NHEAD), blk, SMAV>>>();

    // output projection (x2, BN=64)
    wo_pipe<<<dim3(CH / 64, SEQ / 128, 1), blk, SMWO>>>(out);
}